// round 16
// baseline (speedup 1.0000x reference)
#include <cuda_runtime.h>
#include <cuda_fp16.h>
#include <cstdint>

// ---------------------------------------------------------------------------
// GroupAttention (Swin window attention)
// B=32, N=4096 (64x64), C=128, WS=8 -> G=64 windows, S=64 tokens/window
// heads=4, hd=32.
// Round 16: persistent CTAs — 304 blocks (2/SM), each loops over windows;
// zero wave transitions. R15 body (pipelined fragment loads, W ping-pong,
// Q in registers). Softmax folded to base-2 (exp2f, log2e in Q scale).
// SMEM = X + W + K + V = 87KB, 2 CTAs/SM.
// ---------------------------------------------------------------------------

#define B_    32
#define NTOK  4096
#define C_    128
#define G_    64
#define S_    64
#define NWIN  2048
#define GRID_P 304

__device__ __half g_wq_h[384 * 128];
__device__ __half g_wp_h[128 * 128];

__device__ __forceinline__ int token_index(int g, int s) {
    return ((g >> 3) << 9) + ((s >> 3) << 6) + ((g & 7) << 3) + (s & 7);
}

__device__ __forceinline__ uint32_t h2u(__half2 h) { return *(uint32_t*)&h; }

__device__ __forceinline__ uint32_t smem_u32(const void* p) {
    uint32_t a;
    asm("{ .reg .u64 t; cvta.to.shared.u64 t, %1; cvt.u32.u64 %0, t; }"
        : "=r"(a) : "l"(p));
    return a;
}

__device__ __forceinline__ void mma_f16(float* c, const uint32_t* a,
                                        const uint32_t* b) {
    asm volatile(
        "mma.sync.aligned.m16n8k16.row.col.f32.f16.f16.f32 "
        "{%0,%1,%2,%3}, {%4,%5,%6,%7}, {%8,%9}, {%0,%1,%2,%3};"
        : "+f"(c[0]), "+f"(c[1]), "+f"(c[2]), "+f"(c[3])
        : "r"(a[0]), "r"(a[1]), "r"(a[2]), "r"(a[3]), "r"(b[0]), "r"(b[1]));
}

__device__ __forceinline__ void ldmx4(uint32_t* r, uint32_t addr) {
    asm volatile(
        "ldmatrix.sync.aligned.m8n8.x4.shared.b16 {%0,%1,%2,%3}, [%4];"
        : "=r"(r[0]), "=r"(r[1]), "=r"(r[2]), "=r"(r[3]) : "r"(addr));
}

__device__ __forceinline__ void ldmx4t(uint32_t* r, uint32_t addr) {
    asm volatile(
        "ldmatrix.sync.aligned.m8n8.x4.trans.shared.b16 {%0,%1,%2,%3}, [%4];"
        : "=r"(r[0]), "=r"(r[1]), "=r"(r[2]), "=r"(r[3]) : "r"(addr));
}

__device__ __forceinline__ void cp16(uint32_t dst, const void* src) {
    asm volatile("cp.async.cg.shared.global [%0], [%1], 16;"
                 :: "r"(dst), "l"(src));
}
#define CP_COMMIT() asm volatile("cp.async.commit_group;" ::: "memory")
#define CP_WAIT0()  asm volatile("cp.async.wait_group 0;" ::: "memory")

// row stride in halfwords: 68 words % 32 == 4 -> conflict-free ldmatrix
#define LDH 136

#define OFF_X  0                        // Xs/Oh  [64][136] : 17408
#define OFF_W  17408                    // Ws    [128][136] : 34816
#define OFF_K  52224                    // Kh     [64][136] : 17408  } also the
#define OFF_V  69632                    // Vh     [64][136] : 17408  } W1 buffer
#define SMEM_FUSED 87040                // x2 CTAs = 174KB/SM

// softmax scale folded with log2(e): scores come out in log2 units
#define QSCALE 0.2550437314870259f      // (1/sqrt(32)) * log2(e)

// ---------------------------------------------------------------------------
__global__ void __launch_bounds__(256) cvt_weights(const float* __restrict__ wq,
                                                   const float* __restrict__ wp) {
    int idx = blockIdx.x * 256 + threadIdx.x;    // 16384 float4 slots
    if (idx < 12288) {
        float4 v = ((const float4*)wq)[idx];
        __half2* d = (__half2*)g_wq_h + idx * 2;
        d[0] = __floats2half2_rn(v.x, v.y);
        d[1] = __floats2half2_rn(v.z, v.w);
    } else {
        int j = idx - 12288;
        float4 v = ((const float4*)wp)[j];
        __half2* d = (__half2*)g_wp_h + j * 2;
        d[0] = __floats2half2_rn(v.x, v.y);
        d[1] = __floats2half2_rn(v.z, v.w);
    }
}

// 32x32 warp tile x K=128 GEMM, software-pipelined fragment loads.
__device__ __forceinline__ void gemm128(uint32_t xfrag0, uint32_t xfrag1,
                                        uint32_t wbase, int ncol,
                                        int b_row, int b_k8,
                                        float c[2][4][4]) {
    #pragma unroll
    for (int mi = 0; mi < 2; mi++)
        #pragma unroll
        for (int nj = 0; nj < 4; nj++)
            #pragma unroll
            for (int q = 0; q < 4; q++) c[mi][nj][q] = 0.f;

    const uint32_t wfrag = wbase + (((ncol + b_row) * LDH) + b_k8) * 2;
    const uint32_t wnp = 16 * LDH * 2;

    uint32_t a0[2][4], a1[2][4], b0[2][4], b1[2][4];
    ldmx4(a0[0], xfrag0);
    ldmx4(a1[0], xfrag1);
    ldmx4(b0[0], wfrag);
    ldmx4(b1[0], wfrag + wnp);

    #pragma unroll
    for (int kt = 0; kt < 8; kt++) {
        const int cur = kt & 1, nxt = cur ^ 1;
        if (kt < 7) {
            ldmx4(a0[nxt], xfrag0 + (kt + 1) * 32);
            ldmx4(a1[nxt], xfrag1 + (kt + 1) * 32);
            ldmx4(b0[nxt], wfrag + (kt + 1) * 32);
            ldmx4(b1[nxt], wfrag + wnp + (kt + 1) * 32);
        }
        mma_f16(c[0][0], a0[cur], b0[cur]);
        mma_f16(c[0][1], a0[cur], b0[cur] + 2);
        mma_f16(c[1][0], a1[cur], b0[cur]);
        mma_f16(c[1][1], a1[cur], b0[cur] + 2);
        mma_f16(c[0][2], a0[cur], b1[cur]);
        mma_f16(c[0][3], a0[cur], b1[cur] + 2);
        mma_f16(c[1][2], a1[cur], b1[cur]);
        mma_f16(c[1][3], a1[cur], b1[cur] + 2);
    }
}

// ---------------------------------------------------------------------------
// Persistent fused kernel: 304 CTAs (2/SM), each loops over windows.
// Warp w: GEMM tile rows (w&1)*32 x cols (w>>1)*32; attention rows = tile
// rows, head = w>>1 (Q fragments stay in registers).
// ---------------------------------------------------------------------------
__global__ void __launch_bounds__(256, 2)
fused_all(const float* __restrict__ x, const float* __restrict__ bp,
          float* __restrict__ out) {
    extern __shared__ char sm[];
    __half* Xs = (__half*)(sm + OFF_X);       // X, then O
    __half* Kh = (__half*)(sm + OFF_K);
    __half* Vh = (__half*)(sm + OFF_V);

    const uint32_t xb = smem_u32(sm + OFF_X);
    const uint32_t wb = smem_u32(sm + OFF_W);
    const uint32_t kb = smem_u32(sm + OFF_K); // also base of the W1 buffer
    const uint32_t vb = smem_u32(sm + OFF_V);

    const int tid = threadIdx.x;
    const int wid = tid >> 5, lane = tid & 31;
    const int lr = lane >> 2, lc = lane & 3;

    const int mrow = (wid & 1) * 32;
    const int ncol = (wid >> 1) * 32;
    const int hcol = ncol;

    // ldmatrix lane address components
    const int a_row = lane & 15;
    const int a_k8  = (lane >> 4) << 3;
    const int b_row = ((lane >> 4) << 3) + (lane & 7);
    const int b_k8  = ((lane >> 3) & 1) << 3;
    const int v_row = (lane & 7) + (((lane >> 3) & 1) << 3);
    const int v_c8  = (lane >> 4) << 3;

    // W fill via cp.async: 128 rows x 16 chunks(16B), 8 chunks/thread
    const int wr  = tid >> 4;
    const int wc8 = (tid & 15) * 8;

    const uint32_t xfrag0 = xb + (((mrow + a_row) * LDH) + a_k8) * 2;
    const uint32_t xfrag1 = xfrag0 + 16 * LDH * 2;

    for (int w = blockIdx.x; w < NWIN; w += GRID_P) {
        const int b = w >> 6, g = w & 63;

        // ---- phase 0: W0 -> Ws under the X gather ----
        #pragma unroll
        for (int it = 0; it < 8; it++) {
            int r = wr + it * 16;
            cp16(wb + (r * LDH + wc8) * 2, g_wq_h + (size_t)r * C_ + wc8);
        }
        CP_COMMIT();

        #pragma unroll
        for (int it = 0; it < 8; it++) {
            int fidx = tid + it * 256;        // 2048 float4s: 64 rows x 32
            int s = fidx >> 5;
            int c4 = fidx & 31;
            int n = token_index(g, s);
            float4 v = *(const float4*)(x + ((size_t)b * NTOK + n) * C_ + c4 * 4);
            __half2* dst = (__half2*)(Xs + s * LDH + c4 * 4);
            dst[0] = __floats2half2_rn(v.x, v.y);
            dst[1] = __floats2half2_rn(v.z, v.w);
        }
        CP_WAIT0();
        __syncthreads();                      // (1) X + W0 ready

        // ---- ch0 (Q): W1 -> [Kh:Vh] region under the Q GEMM ----
        #pragma unroll
        for (int it = 0; it < 8; it++) {
            int r = wr + it * 16;
            cp16(kb + (r * LDH + wc8) * 2, g_wq_h + (size_t)(128 + r) * C_ + wc8);
        }
        CP_COMMIT();

        uint32_t qa[2][2][4];
        {
            float cq[2][4][4];
            gemm128(xfrag0, xfrag1, wb, ncol, b_row, b_k8, cq);
            // fold base-2 softmax scale into Q, repack C-frags -> A-frags
            #pragma unroll
            for (int mi = 0; mi < 2; mi++)
                #pragma unroll
                for (int kt = 0; kt < 2; kt++) {
                    qa[mi][kt][0] = h2u(__floats2half2_rn(cq[mi][2 * kt][0] * QSCALE,
                                                          cq[mi][2 * kt][1] * QSCALE));
                    qa[mi][kt][1] = h2u(__floats2half2_rn(cq[mi][2 * kt][2] * QSCALE,
                                                          cq[mi][2 * kt][3] * QSCALE));
                    qa[mi][kt][2] = h2u(__floats2half2_rn(cq[mi][2 * kt + 1][0] * QSCALE,
                                                          cq[mi][2 * kt + 1][1] * QSCALE));
                    qa[mi][kt][3] = h2u(__floats2half2_rn(cq[mi][2 * kt + 1][2] * QSCALE,
                                                          cq[mi][2 * kt + 1][3] * QSCALE));
                }
        }
        CP_WAIT0();
        __syncthreads();                      // (2) ch0 Ws reads done; W1 ready

        // ---- ch1 (K): W2 -> Ws under the K GEMM; K deferred in regs ----
        #pragma unroll
        for (int it = 0; it < 8; it++) {
            int r = wr + it * 16;
            cp16(wb + (r * LDH + wc8) * 2, g_wq_h + (size_t)(256 + r) * C_ + wc8);
        }
        CP_COMMIT();

        float ck[2][4][4];
        gemm128(xfrag0, xfrag1, kb, ncol, b_row, b_k8, ck);   // reads W1
        CP_WAIT0();
        __syncthreads();                      // (3) W1 reads done; W2 ready

        // write deferred K into Kh (over dead W1 rows 0..63)
        #pragma unroll
        for (int mi = 0; mi < 2; mi++)
            #pragma unroll
            for (int nj = 0; nj < 4; nj++) {
                int r = mrow + mi * 16 + lr;
                int col = ncol + nj * 8 + 2 * lc;
                *(__half2*)(Kh + r * LDH + col) =
                    __floats2half2_rn(ck[mi][nj][0], ck[mi][nj][1]);
                *(__half2*)(Kh + (r + 8) * LDH + col) =
                    __floats2half2_rn(ck[mi][nj][2], ck[mi][nj][3]);
            }

        // ---- ch2 (V): from Ws; epilogue -> Vh (dead W1 rows 64..127) ----
        {
            float cv[2][4][4];
            gemm128(xfrag0, xfrag1, wb, ncol, b_row, b_k8, cv);
            #pragma unroll
            for (int mi = 0; mi < 2; mi++)
                #pragma unroll
                for (int nj = 0; nj < 4; nj++) {
                    int r = mrow + mi * 16 + lr;
                    int col = ncol + nj * 8 + 2 * lc;
                    *(__half2*)(Vh + r * LDH + col) =
                        __floats2half2_rn(cv[mi][nj][0], cv[mi][nj][1]);
                    *(__half2*)(Vh + (r + 8) * LDH + col) =
                        __floats2half2_rn(cv[mi][nj][2], cv[mi][nj][3]);
                }
        }
        __syncthreads();                      // (4) K,V ready; Ws reads done

        // ---- Wp -> Ws under the attention phase ----
        #pragma unroll
        for (int it = 0; it < 8; it++) {
            int r = wr + it * 16;
            cp16(wb + (r * LDH + wc8) * 2, g_wp_h + (size_t)r * C_ + wc8);
        }
        CP_COMMIT();

        // ---- attention: 32 rows x head per warp, single pass ----
        float sf[2][8][4];
        #pragma unroll
        for (int mi = 0; mi < 2; mi++)
            #pragma unroll
            for (int nj = 0; nj < 8; nj++)
                #pragma unroll
                for (int q = 0; q < 4; q++) sf[mi][nj][q] = 0.f;

        {
            uint32_t bb[2][4];
            ldmx4(bb[0], kb + ((b_row * LDH) + hcol + b_k8) * 2);
            #pragma unroll
            for (int i = 0; i < 8; i++) {     // i = kt*4 + np
                const int cur = i & 1, nxt = cur ^ 1;
                if (i < 7) {
                    int kt1 = (i + 1) >> 2, np1 = (i + 1) & 3;
                    ldmx4(bb[nxt], kb + (((np1 * 16 + b_row) * LDH) +
                                         hcol + kt1 * 16 + b_k8) * 2);
                }
                const int kt = i >> 2, np = i & 3;
                mma_f16(sf[0][np * 2], qa[0][kt], bb[cur]);
                mma_f16(sf[0][np * 2 + 1], qa[0][kt], bb[cur] + 2);
                mma_f16(sf[1][np * 2], qa[1][kt], bb[cur]);
                mma_f16(sf[1][np * 2 + 1], qa[1][kt], bb[cur] + 2);
            }
        }

        // softmax per m-subtile (scores are in log2 units; use exp2)
        float invlo[2], invhi[2];
        uint32_t ph[2][8][2];
        #pragma unroll
        for (int mi = 0; mi < 2; mi++) {
            float mlo = -1e30f, mhi = -1e30f;
            #pragma unroll
            for (int nj = 0; nj < 8; nj++) {
                mlo = fmaxf(mlo, fmaxf(sf[mi][nj][0], sf[mi][nj][1]));
                mhi = fmaxf(mhi, fmaxf(sf[mi][nj][2], sf[mi][nj][3]));
            }
            mlo = fmaxf(mlo, __shfl_xor_sync(0xffffffffu, mlo, 1));
            mlo = fmaxf(mlo, __shfl_xor_sync(0xffffffffu, mlo, 2));
            mhi = fmaxf(mhi, __shfl_xor_sync(0xffffffffu, mhi, 1));
            mhi = fmaxf(mhi, __shfl_xor_sync(0xffffffffu, mhi, 2));

            float slo = 0.f, shi = 0.f;
            #pragma unroll
            for (int nj = 0; nj < 8; nj++) {
                float e0 = exp2f(sf[mi][nj][0] - mlo);
                float e1 = exp2f(sf[mi][nj][1] - mlo);
                float e2 = exp2f(sf[mi][nj][2] - mhi);
                float e3 = exp2f(sf[mi][nj][3] - mhi);
                slo += e0 + e1;
                shi += e2 + e3;
                ph[mi][nj][0] = h2u(__floats2half2_rn(e0, e1));
                ph[mi][nj][1] = h2u(__floats2half2_rn(e2, e3));
            }
            slo += __shfl_xor_sync(0xffffffffu, slo, 1);
            slo += __shfl_xor_sync(0xffffffffu, slo, 2);
            shi += __shfl_xor_sync(0xffffffffu, shi, 1);
            shi += __shfl_xor_sync(0xffffffffu, shi, 2);
            invlo[mi] = 1.f / slo;
            invhi[mi] = 1.f / shi;
        }

        // O = P V : pipelined over flattened (kt, np) iterations
        float o[2][4][4];
        #pragma unroll
        for (int mi = 0; mi < 2; mi++)
            #pragma unroll
            for (int nj = 0; nj < 4; nj++)
                #pragma unroll
                for (int q = 0; q < 4; q++) o[mi][nj][q] = 0.f;

        {
            uint32_t bb[2][4];
            ldmx4t(bb[0], vb + ((v_row * LDH) + hcol + v_c8) * 2);
            #pragma unroll
            for (int i = 0; i < 8; i++) {     // i = kt*2 + np
                const int cur = i & 1, nxt = cur ^ 1;
                if (i < 7) {
                    int kt1 = (i + 1) >> 1, np1 = (i + 1) & 1;
                    ldmx4t(bb[nxt], vb + (((kt1 * 16 + v_row) * LDH) +
                                          hcol + np1 * 16 + v_c8) * 2);
                }
                const int kt = i >> 1, np = i & 1;
                uint32_t a0[4], a1[4];
                a0[0] = ph[0][2 * kt][0]; a0[1] = ph[0][2 * kt][1];
                a0[2] = ph[0][2 * kt + 1][0]; a0[3] = ph[0][2 * kt + 1][1];
                a1[0] = ph[1][2 * kt][0]; a1[1] = ph[1][2 * kt][1];
                a1[2] = ph[1][2 * kt + 1][0]; a1[3] = ph[1][2 * kt + 1][1];
                mma_f16(o[0][np * 2], a0, bb[cur]);
                mma_f16(o[0][np * 2 + 1], a0, bb[cur] + 2);
                mma_f16(o[1][np * 2], a1, bb[cur]);
                mma_f16(o[1][np * 2 + 1], a1, bb[cur] + 2);
            }
        }

        // normalize + store O into Xs
        __half* Oh = Xs;
        #pragma unroll
        for (int mi = 0; mi < 2; mi++) {
            int r = mrow + mi * 16 + lr;
            #pragma unroll
            for (int nj = 0; nj < 4; nj++) {
                int col = hcol + nj * 8 + 2 * lc;
                *(__half2*)(Oh + r * LDH + col) =
                    __floats2half2_rn(o[mi][nj][0] * invlo[mi],
                                      o[mi][nj][1] * invlo[mi]);
                *(__half2*)(Oh + (r + 8) * LDH + col) =
                    __floats2half2_rn(o[mi][nj][2] * invhi[mi],
                                      o[mi][nj][3] * invhi[mi]);
            }
        }
        CP_WAIT0();
        __syncthreads();                      // (5) O complete; Wp ready

        // ---- proj: single pass, out = O * Wp^T + bias ----
        {
            float c[2][4][4];
            gemm128(xfrag0, xfrag1, wb, ncol, b_row, b_k8, c);

            #pragma unroll
            for (int mi = 0; mi < 2; mi++) {
                int r = mrow + mi * 16 + lr;
                int n0t = token_index(g, r);
                int n1t = token_index(g, r + 8);
                float* r0 = out + ((size_t)b * NTOK + n0t) * C_;
                float* r1 = out + ((size_t)b * NTOK + n1t) * C_;
                #pragma unroll
                for (int nj = 0; nj < 4; nj++) {
                    int col = ncol + nj * 8 + 2 * lc;
                    float bx = bp[col], by = bp[col + 1];
                    *(float2*)(r0 + col) = make_float2(c[mi][nj][0] + bx,
                                                       c[mi][nj][1] + by);
                    *(float2*)(r1 + col) = make_float2(c[mi][nj][2] + bx,
                                                       c[mi][nj][3] + by);
                }
            }
        }
        __syncthreads();                      // (6) proj reads done; Ws/Xs free
    }
}

// ---------------------------------------------------------------------------
extern "C" void kernel_launch(void* const* d_in, const int* in_sizes, int n_in,
                              void* d_out, int out_size) {
    (void)in_sizes; (void)n_in; (void)out_size;
    const float* x      = (const float*)d_in[0];
    const float* w_qkv  = (const float*)d_in[1];
    const float* w_proj = (const float*)d_in[2];
    const float* b_proj = (const float*)d_in[3];
    float* out = (float*)d_out;

    cudaFuncSetAttribute(fused_all,
                         cudaFuncAttributeMaxDynamicSharedMemorySize, SMEM_FUSED);

    cvt_weights<<<64, 256>>>(w_qkv, w_proj);
    fused_all<<<GRID_P, 256, SMEM_FUSED>>>(x, b_proj, out);
}

// round 17
// speedup vs baseline: 1.0343x; 1.0343x over previous
#include <cuda_runtime.h>
#include <cuda_fp16.h>
#include <cstdint>

// ---------------------------------------------------------------------------
// GroupAttention (Swin window attention)
// B=32, N=4096 (64x64), C=128, WS=8 -> G=64 windows, S=64 tokens/window
// heads=4, hd=32.
// Round 17: best-known structure (R15: grid 2048, 5 barriers, pipelined
// fragment loads, W ping-pong through dead K/V buffers, Q in registers)
// + the R16-validated base-2 softmax fold (exp2f, log2e folded into QSCALE).
// Persistence reverted (R16 regression: tail imbalance + extra barrier).
// SMEM = X + W + K + V = 87KB, 2 CTAs/SM.
// ---------------------------------------------------------------------------

#define B_    32
#define NTOK  4096
#define C_    128
#define G_    64
#define S_    64

__device__ __half g_wq_h[384 * 128];
__device__ __half g_wp_h[128 * 128];

__device__ __forceinline__ int token_index(int g, int s) {
    return ((g >> 3) << 9) + ((s >> 3) << 6) + ((g & 7) << 3) + (s & 7);
}

__device__ __forceinline__ uint32_t h2u(__half2 h) { return *(uint32_t*)&h; }

__device__ __forceinline__ uint32_t smem_u32(const void* p) {
    uint32_t a;
    asm("{ .reg .u64 t; cvta.to.shared.u64 t, %1; cvt.u32.u64 %0, t; }"
        : "=r"(a) : "l"(p));
    return a;
}

__device__ __forceinline__ void mma_f16(float* c, const uint32_t* a,
                                        const uint32_t* b) {
    asm volatile(
        "mma.sync.aligned.m16n8k16.row.col.f32.f16.f16.f32 "
        "{%0,%1,%2,%3}, {%4,%5,%6,%7}, {%8,%9}, {%0,%1,%2,%3};"
        : "+f"(c[0]), "+f"(c[1]), "+f"(c[2]), "+f"(c[3])
        : "r"(a[0]), "r"(a[1]), "r"(a[2]), "r"(a[3]), "r"(b[0]), "r"(b[1]));
}

__device__ __forceinline__ void ldmx4(uint32_t* r, uint32_t addr) {
    asm volatile(
        "ldmatrix.sync.aligned.m8n8.x4.shared.b16 {%0,%1,%2,%3}, [%4];"
        : "=r"(r[0]), "=r"(r[1]), "=r"(r[2]), "=r"(r[3]) : "r"(addr));
}

__device__ __forceinline__ void ldmx4t(uint32_t* r, uint32_t addr) {
    asm volatile(
        "ldmatrix.sync.aligned.m8n8.x4.trans.shared.b16 {%0,%1,%2,%3}, [%4];"
        : "=r"(r[0]), "=r"(r[1]), "=r"(r[2]), "=r"(r[3]) : "r"(addr));
}

__device__ __forceinline__ void cp16(uint32_t dst, const void* src) {
    asm volatile("cp.async.cg.shared.global [%0], [%1], 16;"
                 :: "r"(dst), "l"(src));
}
#define CP_COMMIT() asm volatile("cp.async.commit_group;" ::: "memory")
#define CP_WAIT0()  asm volatile("cp.async.wait_group 0;" ::: "memory")

// row stride in halfwords: 68 words % 32 == 4 -> conflict-free ldmatrix
#define LDH 136

#define OFF_X  0                        // Xs/Oh  [64][136] : 17408
#define OFF_W  17408                    // Ws    [128][136] : 34816
#define OFF_K  52224                    // Kh     [64][136] : 17408  } also the
#define OFF_V  69632                    // Vh     [64][136] : 17408  } W1 buffer
#define SMEM_FUSED 87040                // x2 CTAs = 174KB/SM

// softmax scale folded with log2(e): scores come out in log2 units
#define QSCALE 0.2550437314870259f      // (1/sqrt(32)) * log2(e)

// ---------------------------------------------------------------------------
__global__ void __launch_bounds__(256) cvt_weights(const float* __restrict__ wq,
                                                   const float* __restrict__ wp) {
    int idx = blockIdx.x * 256 + threadIdx.x;    // 16384 float4 slots
    if (idx < 12288) {
        float4 v = ((const float4*)wq)[idx];
        __half2* d = (__half2*)g_wq_h + idx * 2;
        d[0] = __floats2half2_rn(v.x, v.y);
        d[1] = __floats2half2_rn(v.z, v.w);
    } else {
        int j = idx - 12288;
        float4 v = ((const float4*)wp)[j];
        __half2* d = (__half2*)g_wp_h + j * 2;
        d[0] = __floats2half2_rn(v.x, v.y);
        d[1] = __floats2half2_rn(v.z, v.w);
    }
}

// 32x32 warp tile x K=128 GEMM, software-pipelined fragment loads:
// kt+1's 4 ldmatrix issue before kt's 8 mma.
__device__ __forceinline__ void gemm128(uint32_t xfrag0, uint32_t xfrag1,
                                        uint32_t wbase, int ncol,
                                        int b_row, int b_k8,
                                        float c[2][4][4]) {
    #pragma unroll
    for (int mi = 0; mi < 2; mi++)
        #pragma unroll
        for (int nj = 0; nj < 4; nj++)
            #pragma unroll
            for (int q = 0; q < 4; q++) c[mi][nj][q] = 0.f;

    const uint32_t wfrag = wbase + (((ncol + b_row) * LDH) + b_k8) * 2;
    const uint32_t wnp = 16 * LDH * 2;

    uint32_t a0[2][4], a1[2][4], b0[2][4], b1[2][4];
    ldmx4(a0[0], xfrag0);
    ldmx4(a1[0], xfrag1);
    ldmx4(b0[0], wfrag);
    ldmx4(b1[0], wfrag + wnp);

    #pragma unroll
    for (int kt = 0; kt < 8; kt++) {
        const int cur = kt & 1, nxt = cur ^ 1;
        if (kt < 7) {
            ldmx4(a0[nxt], xfrag0 + (kt + 1) * 32);
            ldmx4(a1[nxt], xfrag1 + (kt + 1) * 32);
            ldmx4(b0[nxt], wfrag + (kt + 1) * 32);
            ldmx4(b1[nxt], wfrag + wnp + (kt + 1) * 32);
        }
        mma_f16(c[0][0], a0[cur], b0[cur]);
        mma_f16(c[0][1], a0[cur], b0[cur] + 2);
        mma_f16(c[1][0], a1[cur], b0[cur]);
        mma_f16(c[1][1], a1[cur], b0[cur] + 2);
        mma_f16(c[0][2], a0[cur], b1[cur]);
        mma_f16(c[0][3], a0[cur], b1[cur] + 2);
        mma_f16(c[1][2], a1[cur], b1[cur]);
        mma_f16(c[1][3], a1[cur], b1[cur] + 2);
    }
}

// ---------------------------------------------------------------------------
// Fused kernel: one block per window, 256 threads (8 warps), 2 CTAs/SM.
// Warp w: GEMM tile rows (w&1)*32 x cols (w>>1)*32; attention rows = tile
// rows, head = w>>1 (Q fragments stay in registers).
// ---------------------------------------------------------------------------
__global__ void __launch_bounds__(256, 2)
fused_all(const float* __restrict__ x, const float* __restrict__ bp,
          float* __restrict__ out) {
    extern __shared__ char sm[];
    __half* Xs = (__half*)(sm + OFF_X);       // X, then O
    __half* Kh = (__half*)(sm + OFF_K);
    __half* Vh = (__half*)(sm + OFF_V);

    const uint32_t xb = smem_u32(sm + OFF_X);
    const uint32_t wb = smem_u32(sm + OFF_W);
    const uint32_t kb = smem_u32(sm + OFF_K); // also base of the W1 buffer
    const uint32_t vb = smem_u32(sm + OFF_V);

    const int tid = threadIdx.x;
    const int wid = tid >> 5, lane = tid & 31;
    const int lr = lane >> 2, lc = lane & 3;
    const int bg = blockIdx.x;
    const int b = bg >> 6, g = bg & 63;

    const int mrow = (wid & 1) * 32;
    const int ncol = (wid >> 1) * 32;
    const int hcol = ncol;

    // ldmatrix lane address components
    const int a_row = lane & 15;
    const int a_k8  = (lane >> 4) << 3;
    const int b_row = ((lane >> 4) << 3) + (lane & 7);
    const int b_k8  = ((lane >> 3) & 1) << 3;
    const int v_row = (lane & 7) + (((lane >> 3) & 1) << 3);
    const int v_c8  = (lane >> 4) << 3;

    // W fill via cp.async: 128 rows x 16 chunks(16B), 8 chunks/thread
    const int wr  = tid >> 4;
    const int wc8 = (tid & 15) * 8;

    // ---- phase 0: W0 -> Ws under the X gather ----
    #pragma unroll
    for (int it = 0; it < 8; it++) {
        int r = wr + it * 16;
        cp16(wb + (r * LDH + wc8) * 2, g_wq_h + (size_t)r * C_ + wc8);
    }
    CP_COMMIT();

    #pragma unroll
    for (int it = 0; it < 8; it++) {
        int fidx = tid + it * 256;            // 2048 float4s: 64 rows x 32
        int s = fidx >> 5;
        int c4 = fidx & 31;
        int n = token_index(g, s);
        float4 v = *(const float4*)(x + ((size_t)b * NTOK + n) * C_ + c4 * 4);
        __half2* dst = (__half2*)(Xs + s * LDH + c4 * 4);
        dst[0] = __floats2half2_rn(v.x, v.y);
        dst[1] = __floats2half2_rn(v.z, v.w);
    }
    CP_WAIT0();
    __syncthreads();                          // (1) X + W0 ready

    const uint32_t xfrag0 = xb + (((mrow + a_row) * LDH) + a_k8) * 2;
    const uint32_t xfrag1 = xfrag0 + 16 * LDH * 2;

    // ---- ch0 (Q): W1 -> [Kh:Vh] region under the Q GEMM ----
    #pragma unroll
    for (int it = 0; it < 8; it++) {
        int r = wr + it * 16;
        cp16(kb + (r * LDH + wc8) * 2, g_wq_h + (size_t)(128 + r) * C_ + wc8);
    }
    CP_COMMIT();

    uint32_t qa[2][2][4];
    {
        float cq[2][4][4];
        gemm128(xfrag0, xfrag1, wb, ncol, b_row, b_k8, cq);
        // fold base-2 softmax scale into Q, repack C-frags -> A-frags
        #pragma unroll
        for (int mi = 0; mi < 2; mi++)
            #pragma unroll
            for (int kt = 0; kt < 2; kt++) {
                qa[mi][kt][0] = h2u(__floats2half2_rn(cq[mi][2 * kt][0] * QSCALE,
                                                      cq[mi][2 * kt][1] * QSCALE));
                qa[mi][kt][1] = h2u(__floats2half2_rn(cq[mi][2 * kt][2] * QSCALE,
                                                      cq[mi][2 * kt][3] * QSCALE));
                qa[mi][kt][2] = h2u(__floats2half2_rn(cq[mi][2 * kt + 1][0] * QSCALE,
                                                      cq[mi][2 * kt + 1][1] * QSCALE));
                qa[mi][kt][3] = h2u(__floats2half2_rn(cq[mi][2 * kt + 1][2] * QSCALE,
                                                      cq[mi][2 * kt + 1][3] * QSCALE));
            }
    }
    CP_WAIT0();
    __syncthreads();                          // (2) ch0 Ws reads done; W1 ready

    // ---- ch1 (K): W2 -> Ws under the K GEMM; K result deferred in regs ----
    #pragma unroll
    for (int it = 0; it < 8; it++) {
        int r = wr + it * 16;
        cp16(wb + (r * LDH + wc8) * 2, g_wq_h + (size_t)(256 + r) * C_ + wc8);
    }
    CP_COMMIT();

    float ck[2][4][4];
    gemm128(xfrag0, xfrag1, kb, ncol, b_row, b_k8, ck);   // reads W1
    CP_WAIT0();
    __syncthreads();                          // (3) W1 reads done; W2 ready

    // write deferred K into Kh (over dead W1 rows 0..63)
    #pragma unroll
    for (int mi = 0; mi < 2; mi++)
        #pragma unroll
        for (int nj = 0; nj < 4; nj++) {
            int r = mrow + mi * 16 + lr;
            int col = ncol + nj * 8 + 2 * lc;
            *(__half2*)(Kh + r * LDH + col) =
                __floats2half2_rn(ck[mi][nj][0], ck[mi][nj][1]);
            *(__half2*)(Kh + (r + 8) * LDH + col) =
                __floats2half2_rn(ck[mi][nj][2], ck[mi][nj][3]);
        }

    // ---- ch2 (V): compute from Ws; epilogue -> Vh (dead W1 rows 64..127) ----
    {
        float cv[2][4][4];
        gemm128(xfrag0, xfrag1, wb, ncol, b_row, b_k8, cv);
        #pragma unroll
        for (int mi = 0; mi < 2; mi++)
            #pragma unroll
            for (int nj = 0; nj < 4; nj++) {
                int r = mrow + mi * 16 + lr;
                int col = ncol + nj * 8 + 2 * lc;
                *(__half2*)(Vh + r * LDH + col) =
                    __floats2half2_rn(cv[mi][nj][0], cv[mi][nj][1]);
                *(__half2*)(Vh + (r + 8) * LDH + col) =
                    __floats2half2_rn(cv[mi][nj][2], cv[mi][nj][3]);
            }
    }
    __syncthreads();                          // (4) K,V ready; ch2 Ws reads done

    // ---- Wp -> Ws under the attention phase ----
    #pragma unroll
    for (int it = 0; it < 8; it++) {
        int r = wr + it * 16;
        cp16(wb + (r * LDH + wc8) * 2, g_wp_h + (size_t)r * C_ + wc8);
    }
    CP_COMMIT();

    // ---- attention: 32 rows x head per warp, single pass ----
    // S = Q K^T : pipelined over flattened (kt, np) iterations
    float sf[2][8][4];
    #pragma unroll
    for (int mi = 0; mi < 2; mi++)
        #pragma unroll
        for (int nj = 0; nj < 8; nj++)
            #pragma unroll
            for (int q = 0; q < 4; q++) sf[mi][nj][q] = 0.f;

    {
        uint32_t bb[2][4];
        ldmx4(bb[0], kb + ((b_row * LDH) + hcol + b_k8) * 2);
        #pragma unroll
        for (int i = 0; i < 8; i++) {         // i = kt*4 + np
            const int cur = i & 1, nxt = cur ^ 1;
            if (i < 7) {
                int kt1 = (i + 1) >> 2, np1 = (i + 1) & 3;
                ldmx4(bb[nxt], kb + (((np1 * 16 + b_row) * LDH) +
                                     hcol + kt1 * 16 + b_k8) * 2);
            }
            const int kt = i >> 2, np = i & 3;
            mma_f16(sf[0][np * 2], qa[0][kt], bb[cur]);
            mma_f16(sf[0][np * 2 + 1], qa[0][kt], bb[cur] + 2);
            mma_f16(sf[1][np * 2], qa[1][kt], bb[cur]);
            mma_f16(sf[1][np * 2 + 1], qa[1][kt], bb[cur] + 2);
        }
    }

    // softmax per m-subtile (scores are in log2 units; use exp2)
    float invlo[2], invhi[2];
    uint32_t ph[2][8][2];
    #pragma unroll
    for (int mi = 0; mi < 2; mi++) {
        float mlo = -1e30f, mhi = -1e30f;
        #pragma unroll
        for (int nj = 0; nj < 8; nj++) {
            mlo = fmaxf(mlo, fmaxf(sf[mi][nj][0], sf[mi][nj][1]));
            mhi = fmaxf(mhi, fmaxf(sf[mi][nj][2], sf[mi][nj][3]));
        }
        mlo = fmaxf(mlo, __shfl_xor_sync(0xffffffffu, mlo, 1));
        mlo = fmaxf(mlo, __shfl_xor_sync(0xffffffffu, mlo, 2));
        mhi = fmaxf(mhi, __shfl_xor_sync(0xffffffffu, mhi, 1));
        mhi = fmaxf(mhi, __shfl_xor_sync(0xffffffffu, mhi, 2));

        float slo = 0.f, shi = 0.f;
        #pragma unroll
        for (int nj = 0; nj < 8; nj++) {
            float e0 = exp2f(sf[mi][nj][0] - mlo);
            float e1 = exp2f(sf[mi][nj][1] - mlo);
            float e2 = exp2f(sf[mi][nj][2] - mhi);
            float e3 = exp2f(sf[mi][nj][3] - mhi);
            slo += e0 + e1;
            shi += e2 + e3;
            ph[mi][nj][0] = h2u(__floats2half2_rn(e0, e1));
            ph[mi][nj][1] = h2u(__floats2half2_rn(e2, e3));
        }
        slo += __shfl_xor_sync(0xffffffffu, slo, 1);
        slo += __shfl_xor_sync(0xffffffffu, slo, 2);
        shi += __shfl_xor_sync(0xffffffffu, shi, 1);
        shi += __shfl_xor_sync(0xffffffffu, shi, 2);
        invlo[mi] = 1.f / slo;
        invhi[mi] = 1.f / shi;
    }

    // O = P V : pipelined over flattened (kt, np) iterations
    float o[2][4][4];
    #pragma unroll
    for (int mi = 0; mi < 2; mi++)
        #pragma unroll
        for (int nj = 0; nj < 4; nj++)
            #pragma unroll
            for (int q = 0; q < 4; q++) o[mi][nj][q] = 0.f;

    {
        uint32_t bb[2][4];
        ldmx4t(bb[0], vb + ((v_row * LDH) + hcol + v_c8) * 2);
        #pragma unroll
        for (int i = 0; i < 8; i++) {         // i = kt*2 + np
            const int cur = i & 1, nxt = cur ^ 1;
            if (i < 7) {
                int kt1 = (i + 1) >> 1, np1 = (i + 1) & 1;
                ldmx4t(bb[nxt], vb + (((kt1 * 16 + v_row) * LDH) +
                                      hcol + np1 * 16 + v_c8) * 2);
            }
            const int kt = i >> 1, np = i & 1;
            uint32_t a0[4], a1[4];
            a0[0] = ph[0][2 * kt][0]; a0[1] = ph[0][2 * kt][1];
            a0[2] = ph[0][2 * kt + 1][0]; a0[3] = ph[0][2 * kt + 1][1];
            a1[0] = ph[1][2 * kt][0]; a1[1] = ph[1][2 * kt][1];
            a1[2] = ph[1][2 * kt + 1][0]; a1[3] = ph[1][2 * kt + 1][1];
            mma_f16(o[0][np * 2], a0, bb[cur]);
            mma_f16(o[0][np * 2 + 1], a0, bb[cur] + 2);
            mma_f16(o[1][np * 2], a1, bb[cur]);
            mma_f16(o[1][np * 2 + 1], a1, bb[cur] + 2);
        }
    }

    // normalize + store O into Xs
    __half* Oh = Xs;
    #pragma unroll
    for (int mi = 0; mi < 2; mi++) {
        int r = mrow + mi * 16 + lr;
        #pragma unroll
        for (int nj = 0; nj < 4; nj++) {
            int col = hcol + nj * 8 + 2 * lc;
            *(__half2*)(Oh + r * LDH + col) =
                __floats2half2_rn(o[mi][nj][0] * invlo[mi],
                                  o[mi][nj][1] * invlo[mi]);
            *(__half2*)(Oh + (r + 8) * LDH + col) =
                __floats2half2_rn(o[mi][nj][2] * invhi[mi],
                                  o[mi][nj][3] * invhi[mi]);
        }
    }
    CP_WAIT0();
    __syncthreads();                          // (5) O complete; Wp ready

    // ---- proj: single pass, out = O * Wp^T + bias ----
    {
        float c[2][4][4];
        gemm128(xfrag0, xfrag1, wb, ncol, b_row, b_k8, c);

        #pragma unroll
        for (int mi = 0; mi < 2; mi++) {
            int r = mrow + mi * 16 + lr;
            int n0t = token_index(g, r);
            int n1t = token_index(g, r + 8);
            float* r0 = out + ((size_t)b * NTOK + n0t) * C_;
            float* r1 = out + ((size_t)b * NTOK + n1t) * C_;
            #pragma unroll
            for (int nj = 0; nj < 4; nj++) {
                int col = ncol + nj * 8 + 2 * lc;
                float bx = bp[col], by = bp[col + 1];
                *(float2*)(r0 + col) = make_float2(c[mi][nj][0] + bx,
                                                   c[mi][nj][1] + by);
                *(float2*)(r1 + col) = make_float2(c[mi][nj][2] + bx,
                                                   c[mi][nj][3] + by);
            }
        }
    }
}

// ---------------------------------------------------------------------------
extern "C" void kernel_launch(void* const* d_in, const int* in_sizes, int n_in,
                              void* d_out, int out_size) {
    (void)in_sizes; (void)n_in; (void)out_size;
    const float* x      = (const float*)d_in[0];
    const float* w_qkv  = (const float*)d_in[1];
    const float* w_proj = (const float*)d_in[2];
    const float* b_proj = (const float*)d_in[3];
    float* out = (float*)d_out;

    cudaFuncSetAttribute(fused_all,
                         cudaFuncAttributeMaxDynamicSharedMemorySize, SMEM_FUSED);

    cvt_weights<<<64, 256>>>(w_qkv, w_proj);
    fused_all<<<B_ * G_, 256, SMEM_FUSED>>>(x, b_proj, out);
}